// round 1
// baseline (speedup 1.0000x reference)
#include <cuda_runtime.h>
#include <cuda_fp16.h>
#include <mma.h>

using namespace nvcuda;

// ---------------- problem constants ----------------
#define BROWS 4096
#define NIN   4096
#define NOUT  4096
#define KTOT  4122
#define KPAD  4128   // pad K to multiple of 32 for the GEMM

// band lengths / column offsets in the concatenated coeff matrix C
// [cA4 | cD4 | cD3 | cD2 | cD1]
#define L_CA4 262
#define L_CD4 262
#define L_CD3 518
#define L_CD2 1029
#define L_CD1 2051
#define OFF_CA4 0
#define OFF_CD4 262
#define OFF_CD3 524
#define OFF_CD2 1042
#define OFF_CD1 2071

// ---------------- scratch (no allocs allowed -> device globals) ----------------
__device__ float  g_cA1[(size_t)BROWS * 2051];
__device__ float  g_cA2[(size_t)BROWS * 1029];
__device__ float  g_cA3[(size_t)BROWS * 518];
__device__ __half g_C  [(size_t)BROWS * KPAD];   // coeffs, fp16, row-major [4096, 4128]
__device__ __half g_B  [(size_t)KPAD  * NOUT];   // stacked bases, fp16, row-major [4128, 4096]

__constant__ float c_lo[8] = {
    -0.010597401784997278f,  0.032883011666982945f,  0.030841381835986965f,
    -0.18703481171888114f,  -0.02798376941698385f,   0.6308807679295904f,
     0.7148465705525415f,    0.23037781330885523f };
__constant__ float c_hi[8] = {
    -0.23037781330885523f,   0.7148465705525415f,   -0.6308807679295904f,
    -0.02798376941698385f,   0.18703481171888114f,   0.030841381835986965f,
    -0.032883011666982945f, -0.010597401784997278f };

// ---------------- DWT: one level, db4, pywt 'symmetric' ----------------
// out[j] = sum_{m=0..7} filt[m] * E[8 + 2j - m]
// E[i] = a[6-i] if i<7 ; a[i-7] if i<Nin+7 ; a[2*Nin+6-i] otherwise
__global__ void dwt_level_kernel(const float* __restrict__ in, int Nin, int Nout,
                                 float* __restrict__ cA_f32,     // may be null
                                 __half* __restrict__ C,
                                 int cA_col,                     // -1 = don't write cA to C
                                 int cD_col)
{
    int j   = blockIdx.x * blockDim.x + threadIdx.x;
    int row = blockIdx.y;
    if (j >= Nout) return;

    const float* a = in + (size_t)row * Nin;
    float sLo = 0.f, sHi = 0.f;
#pragma unroll
    for (int m = 0; m < 8; m++) {
        int i = 8 + 2 * j - m;
        int idx;
        if (i < 7)            idx = 6 - i;
        else if (i < Nin + 7) idx = i - 7;
        else                  idx = 2 * Nin + 6 - i;
        float v = __ldg(a + idx);
        sLo = fmaf(c_lo[m], v, sLo);
        sHi = fmaf(c_hi[m], v, sHi);
    }
    if (cA_f32)     cA_f32[(size_t)row * Nout + j] = sLo;
    if (cA_col >= 0) C[(size_t)row * KPAD + cA_col + j] = __float2half_rn(sLo);
    C[(size_t)row * KPAD + cD_col + j] = __float2half_rn(sHi);
}

// zero the 6 padding columns of C (cols 4122..4127)
__global__ void zero_pad_kernel(__half* __restrict__ C)
{
    int row = blockIdx.x * blockDim.x + threadIdx.x;
    if (row >= BROWS) return;
#pragma unroll
    for (int c = KTOT; c < KPAD; c++)
        C[(size_t)row * KPAD + c] = __float2half_rn(0.f);
}

// ---------------- pack bases -> fp16 stacked [KPAD, 4096] ----------------
__global__ void pack_b_kernel(const float* __restrict__ b0, const float* __restrict__ b1,
                              const float* __restrict__ b2, const float* __restrict__ b3,
                              const float* __restrict__ b4, __half* __restrict__ Bh)
{
    int n = (blockIdx.x * blockDim.x + threadIdx.x) * 8;   // 8 columns per thread
    int k = blockIdx.y;
    if (n >= NOUT) return;

    const float* src = nullptr; int r = 0;
    if      (k < OFF_CD4) { src = b0; r = k - OFF_CA4; }
    else if (k < OFF_CD3) { src = b1; r = k - OFF_CD4; }
    else if (k < OFF_CD2) { src = b2; r = k - OFF_CD3; }
    else if (k < OFF_CD1) { src = b3; r = k - OFF_CD2; }
    else if (k < KTOT)    { src = b4; r = k - OFF_CD1; }

    __half2 h[4];
    if (src) {
        const float4* p = (const float4*)(src + (size_t)r * NOUT + n);
        float4 v0 = p[0], v1 = p[1];
        h[0] = __floats2half2_rn(v0.x, v0.y);
        h[1] = __floats2half2_rn(v0.z, v0.w);
        h[2] = __floats2half2_rn(v1.x, v1.y);
        h[3] = __floats2half2_rn(v1.z, v1.w);
    } else {
        h[0] = h[1] = h[2] = h[3] = __half2half2(__float2half_rn(0.f));
    }
    *(int4*)(Bh + (size_t)k * NOUT + n) = *(int4*)h;
}

// ---------------- GEMM: [4096,4128]x[4128,4096] fp16 -> fp32 ----------------
// 128x128 block tile, BK=32, 256 threads (8 warps: 4 x 32 rows, 2 x 64 cols),
// double-buffered smem, register prefetch, one barrier per K-iteration.
#define BM 128
#define BN 128
#define BK 32

__global__ void __launch_bounds__(256, 2)
gemm_kernel(const __half* __restrict__ A, const __half* __restrict__ Bm,
            float* __restrict__ C)
{
    constexpr int M = BROWS, N = NOUT, K = KPAD;
    __shared__ __half As[2][BM][BK + 8];
    __shared__ __half Bs[2][BK][BN + 8];

    const int tid = threadIdx.x;
    const int wid = tid >> 5;
    const int wm  = wid & 3;   // 0..3 -> 32-row slice
    const int wn  = wid >> 2;  // 0..1 -> 64-col slice
    const int rowBase = blockIdx.y * BM;
    const int colBase = blockIdx.x * BN;

    // loader geometry (int4 = 8 halves per vector, 2 vectors/thread per tile)
    const int av0 = tid, av1 = tid + 256;
    const int ar0 = av0 >> 2, ac0 = (av0 & 3) * 8;
    const int ar1 = av1 >> 2, ac1 = (av1 & 3) * 8;
    const int br0 = av0 >> 4, bc0 = (av0 & 15) * 8;
    const int br1 = av1 >> 4, bc1 = (av1 & 15) * 8;

    const __half* Ag = A + (size_t)rowBase * K;
    const __half* Bg = Bm + colBase;

    wmma::fragment<wmma::accumulator, 16, 16, 16, float> acc[2][4];
#pragma unroll
    for (int i = 0; i < 2; i++)
#pragma unroll
        for (int j = 0; j < 4; j++) wmma::fill_fragment(acc[i][j], 0.0f);

    int4 ra0 = *(const int4*)(Ag + (size_t)ar0 * K + ac0);
    int4 ra1 = *(const int4*)(Ag + (size_t)ar1 * K + ac1);
    int4 rb0 = *(const int4*)(Bg + (size_t)br0 * N + bc0);
    int4 rb1 = *(const int4*)(Bg + (size_t)br1 * N + bc1);
    *(int4*)&As[0][ar0][ac0] = ra0;
    *(int4*)&As[0][ar1][ac1] = ra1;
    *(int4*)&Bs[0][br0][bc0] = rb0;
    *(int4*)&Bs[0][br1][bc1] = rb1;
    __syncthreads();

    constexpr int NT = K / BK;   // 129
    int buf = 0;
    for (int t = 0; t < NT; t++) {
        if (t + 1 < NT) {
            const int kb = (t + 1) * BK;
            ra0 = *(const int4*)(Ag + (size_t)ar0 * K + kb + ac0);
            ra1 = *(const int4*)(Ag + (size_t)ar1 * K + kb + ac1);
            rb0 = *(const int4*)(Bg + (size_t)(kb + br0) * N + bc0);
            rb1 = *(const int4*)(Bg + (size_t)(kb + br1) * N + bc1);
        }
#pragma unroll
        for (int kk = 0; kk < BK; kk += 16) {
            wmma::fragment<wmma::matrix_a, 16, 16, 16, __half, wmma::row_major> af[2];
            wmma::fragment<wmma::matrix_b, 16, 16, 16, __half, wmma::row_major> bf[4];
#pragma unroll
            for (int i = 0; i < 2; i++)
                wmma::load_matrix_sync(af[i], &As[buf][wm * 32 + i * 16][kk], BK + 8);
#pragma unroll
            for (int j = 0; j < 4; j++)
                wmma::load_matrix_sync(bf[j], &Bs[buf][kk][wn * 64 + j * 16], BN + 8);
#pragma unroll
            for (int i = 0; i < 2; i++)
#pragma unroll
                for (int j = 0; j < 4; j++)
                    wmma::mma_sync(acc[i][j], af[i], bf[j], acc[i][j]);
        }
        if (t + 1 < NT) {
            buf ^= 1;
            *(int4*)&As[buf][ar0][ac0] = ra0;
            *(int4*)&As[buf][ar1][ac1] = ra1;
            *(int4*)&Bs[buf][br0][bc0] = rb0;
            *(int4*)&Bs[buf][br1][bc1] = rb1;
            __syncthreads();
        }
    }

#pragma unroll
    for (int i = 0; i < 2; i++)
#pragma unroll
        for (int j = 0; j < 4; j++) {
            float* cp = C + (size_t)(rowBase + wm * 32 + i * 16) * N
                          + colBase + wn * 64 + j * 16;
            wmma::store_matrix_sync(cp, acc[i][j], N, wmma::mem_row_major);
        }
}

// ---------------- launch ----------------
extern "C" void kernel_launch(void* const* d_in, const int* in_sizes, int n_in,
                              void* d_out, int out_size)
{
    const float* x  = (const float*)d_in[0];
    const float* b0 = (const float*)d_in[1];
    const float* b1 = (const float*)d_in[2];
    const float* b2 = (const float*)d_in[3];
    const float* b3 = (const float*)d_in[4];
    const float* b4 = (const float*)d_in[5];
    float* out = (float*)d_out;

    float  *cA1, *cA2, *cA3;
    __half *Cm, *Bm;
    cudaGetSymbolAddress((void**)&cA1, g_cA1);
    cudaGetSymbolAddress((void**)&cA2, g_cA2);
    cudaGetSymbolAddress((void**)&cA3, g_cA3);
    cudaGetSymbolAddress((void**)&Cm,  g_C);
    cudaGetSymbolAddress((void**)&Bm,  g_B);

    // 4 DWT levels: 4096 -> 2051 -> 1029 -> 518 -> 262
    dwt_level_kernel<<<dim3((2051 + 255) / 256, BROWS), 256>>>(x,   4096, 2051, cA1, Cm, -1,      OFF_CD1);
    dwt_level_kernel<<<dim3((1029 + 255) / 256, BROWS), 256>>>(cA1, 2051, 1029, cA2, Cm, -1,      OFF_CD2);
    dwt_level_kernel<<<dim3(( 518 + 255) / 256, BROWS), 256>>>(cA2, 1029,  518, cA3, Cm, -1,      OFF_CD3);
    dwt_level_kernel<<<dim3(( 262 + 255) / 256, BROWS), 256>>>(cA3,  518,  262, nullptr, Cm, OFF_CA4, OFF_CD4);

    zero_pad_kernel<<<(BROWS + 255) / 256, 256>>>(Cm);

    pack_b_kernel<<<dim3(NOUT / (256 * 8), KPAD), 256>>>(b0, b1, b2, b3, b4, Bm);

    gemm_kernel<<<dim3(NOUT / BN, BROWS / BM), 256>>>(Cm, Bm, out);
}